// round 1
// baseline (speedup 1.0000x reference)
#include <cuda_runtime.h>

#define NN  100000
#define EE  3200000
#define FIN 128
#define H1  16
#define H2  8
#define NEG 0.2f

// ---------------- scratch (device globals: no allocation allowed) ------------
__device__ float g_h1[NN * H1];
__device__ float g_e1s[NN];
__device__ float g_e1d[NN];
__device__ float g_acc1[NN * H1];
__device__ float g_s1[NN];
__device__ float g_h2[NN * H2];
__device__ float g_e2s[NN];
__device__ float g_e2d[NN];
__device__ float g_acc2[NN * H2];
__device__ float g_s2[NN];
__device__ int   g_is64;

// ---------------- helpers ----------------------------------------------------
__device__ __forceinline__ float lrelu(float e) { return e > 0.f ? e : NEG * e; }

__device__ __forceinline__ void atomic_add_f4(float4* p, float4 v) {
#if __CUDA_ARCH__ >= 900
    atomicAdd(p, v);
#else
    atomicAdd(&p->x, v.x); atomicAdd(&p->y, v.y);
    atomicAdd(&p->z, v.z); atomicAdd(&p->w, v.w);
#endif
}

// Detect int64 vs int32 edge_index layout: for int64 (values < 2^31), every odd
// 32-bit word is the zero high-half. For int32, odd words are dst node ids
// (prob. of 128 consecutive zeros ~ (1e-5)^128 = 0). Deterministic per launch.
__global__ void k_detect(const int* __restrict__ ei) {
    int lane = threadIdx.x;            // one warp
    int any = 0;
    #pragma unroll
    for (int i = 0; i < 4; i++) {
        int idx = 2 * (lane * 4 + i) + 1;   // odd words 1,3,...,255
        any |= ei[idx];
    }
    unsigned b = __ballot_sync(0xffffffffu, any != 0);
    if (lane == 0) g_is64 = (b == 0u) ? 1 : 0;
}

// ---------------- layer 1 node kernel: h1 = x@W1, attention logits, self-loop init
// One warp per node. x row (128 floats) loaded as one float4 per lane (coalesced).
__global__ void k_l1_node(const float* __restrict__ x,
                          const float* __restrict__ W1,
                          const float* __restrict__ a1s,
                          const float* __restrict__ a1d) {
    __shared__ float Wt[H1 * FIN];     // transposed: [j][k]
    __shared__ float as[H1], ad[H1];
    int tid = threadIdx.x;
    for (int i = tid; i < H1 * FIN; i += blockDim.x) {
        int j = i / FIN, k = i - j * FIN;
        Wt[i] = W1[k * H1 + j];
    }
    if (tid < H1) { as[tid] = a1s[tid]; ad[tid] = a1d[tid]; }
    __syncthreads();

    int warp = tid >> 5, lane = tid & 31;
    int node = blockIdx.x * (blockDim.x >> 5) + warp;
    if (node >= NN) return;

    float4 xv = ((const float4*)x)[node * 32 + lane];

    float acc[H1];
    #pragma unroll
    for (int j = 0; j < H1; j++) {
        float4 w = ((const float4*)Wt)[j * 32 + lane];   // LDS.128, conflict-free
        acc[j] = xv.x * w.x + xv.y * w.y + xv.z * w.z + xv.w * w.w;
    }
    #pragma unroll
    for (int j = 0; j < H1; j++) {
        #pragma unroll
        for (int off = 16; off; off >>= 1)
            acc[j] += __shfl_xor_sync(0xffffffffu, acc[j], off);
    }
    if (lane == 0) {
        float es = 0.f, ed = 0.f;
        #pragma unroll
        for (int j = 0; j < H1; j++) { es += acc[j] * as[j]; ed += acc[j] * ad[j]; }
        g_e1s[node] = es;
        g_e1d[node] = ed;
        float w = __expf(lrelu(es + ed));      // self-loop weight
        g_s1[node] = w;
        #pragma unroll
        for (int j = 0; j < H1; j++) {
            g_h1[node * H1 + j]   = acc[j];
            g_acc1[node * H1 + j] = w * acc[j];
        }
    }
}

// ---------------- layer 1 edge pass: softmax-weighted scatter (no max shift) --
__global__ void k_edge1(const int* __restrict__ ei) {
    int e = blockIdx.x * blockDim.x + threadIdx.x;
    if (e >= EE) return;
    int s, d;
    if (g_is64) { int4 v = __ldg((const int4*)ei + e); s = v.x; d = v.z; }
    else        { int2 v = __ldg((const int2*)ei + e); s = v.x; d = v.y; }

    float w = __expf(lrelu(__ldg(&g_e1s[s]) + __ldg(&g_e1d[d])));
    atomicAdd(&g_s1[d], w);

    const float4* hs = (const float4*)(g_h1 + s * H1);
    float4*       ac = (float4*)(g_acc1 + d * H1);
    #pragma unroll
    for (int q = 0; q < 4; q++) {
        float4 h = __ldg(hs + q);
        atomic_add_f4(ac + q, make_float4(w * h.x, w * h.y, w * h.z, w * h.w));
    }
}

// ---------------- layer 2 node kernel: normalize, relu, h2 = o@W2, logits, self-loop
__global__ void k_l2_node(const float* __restrict__ W2,
                          const float* __restrict__ a2s,
                          const float* __restrict__ a2d,
                          const float* __restrict__ b1) {
    __shared__ float Ws[H1 * H2];
    __shared__ float as[H2], ad[H2], bs[H1];
    int tid = threadIdx.x;
    if (tid < H1 * H2) Ws[tid] = W2[tid];
    if (tid < H2) { as[tid] = a2s[tid]; ad[tid] = a2d[tid]; }
    if (tid < H1) bs[tid] = b1[tid];
    __syncthreads();

    int n = blockIdx.x * blockDim.x + tid;
    if (n >= NN) return;

    float inv = 1.f / g_s1[n];
    const float4* a4 = (const float4*)(g_acc1 + n * H1);
    float o[H1];
    #pragma unroll
    for (int q = 0; q < 4; q++) {
        float4 v = a4[q];
        float t;
        t = fmaf(v.x, inv, bs[4 * q + 0]); o[4 * q + 0] = t > 0.f ? t : 0.f;
        t = fmaf(v.y, inv, bs[4 * q + 1]); o[4 * q + 1] = t > 0.f ? t : 0.f;
        t = fmaf(v.z, inv, bs[4 * q + 2]); o[4 * q + 2] = t > 0.f ? t : 0.f;
        t = fmaf(v.w, inv, bs[4 * q + 3]); o[4 * q + 3] = t > 0.f ? t : 0.f;
    }
    float h2[H2];
    #pragma unroll
    for (int j = 0; j < H2; j++) {
        float sum = 0.f;
        #pragma unroll
        for (int k = 0; k < H1; k++) sum = fmaf(o[k], Ws[k * H2 + j], sum);
        h2[j] = sum;
    }
    float es = 0.f, ed = 0.f;
    #pragma unroll
    for (int j = 0; j < H2; j++) { es = fmaf(h2[j], as[j], es); ed = fmaf(h2[j], ad[j], ed); }
    g_e2s[n] = es;
    g_e2d[n] = ed;
    float w = __expf(lrelu(es + ed));
    g_s2[n] = w;
    float4* hv = (float4*)(g_h2 + n * H2);
    float4* av = (float4*)(g_acc2 + n * H2);
    hv[0] = make_float4(h2[0], h2[1], h2[2], h2[3]);
    hv[1] = make_float4(h2[4], h2[5], h2[6], h2[7]);
    av[0] = make_float4(w * h2[0], w * h2[1], w * h2[2], w * h2[3]);
    av[1] = make_float4(w * h2[4], w * h2[5], w * h2[6], w * h2[7]);
}

// ---------------- layer 2 edge pass ------------------------------------------
__global__ void k_edge2(const int* __restrict__ ei) {
    int e = blockIdx.x * blockDim.x + threadIdx.x;
    if (e >= EE) return;
    int s, d;
    if (g_is64) { int4 v = __ldg((const int4*)ei + e); s = v.x; d = v.z; }
    else        { int2 v = __ldg((const int2*)ei + e); s = v.x; d = v.y; }

    float w = __expf(lrelu(__ldg(&g_e2s[s]) + __ldg(&g_e2d[d])));
    atomicAdd(&g_s2[d], w);

    const float4* hs = (const float4*)(g_h2 + s * H2);
    float4*       ac = (float4*)(g_acc2 + d * H2);
    #pragma unroll
    for (int q = 0; q < 2; q++) {
        float4 h = __ldg(hs + q);
        atomic_add_f4(ac + q, make_float4(w * h.x, w * h.y, w * h.z, w * h.w));
    }
}

// ---------------- final: normalize, relu, project to scalar ------------------
__global__ void k_final(const float* __restrict__ Wf,
                        const float* __restrict__ bf,
                        const float* __restrict__ b2,
                        float* __restrict__ out) {
    __shared__ float wf[H2], bs[H2], bfv;
    int tid = threadIdx.x;
    if (tid < H2) { wf[tid] = Wf[tid]; bs[tid] = b2[tid]; }
    if (tid == 0) bfv = bf[0];
    __syncthreads();

    int n = blockIdx.x * blockDim.x + tid;
    if (n >= NN) return;

    float inv = 1.f / g_s2[n];
    const float4* a4 = (const float4*)(g_acc2 + n * H2);
    float4 v0 = a4[0], v1 = a4[1];
    float o[H2];
    float t;
    t = fmaf(v0.x, inv, bs[0]); o[0] = t > 0.f ? t : 0.f;
    t = fmaf(v0.y, inv, bs[1]); o[1] = t > 0.f ? t : 0.f;
    t = fmaf(v0.z, inv, bs[2]); o[2] = t > 0.f ? t : 0.f;
    t = fmaf(v0.w, inv, bs[3]); o[3] = t > 0.f ? t : 0.f;
    t = fmaf(v1.x, inv, bs[4]); o[4] = t > 0.f ? t : 0.f;
    t = fmaf(v1.y, inv, bs[5]); o[5] = t > 0.f ? t : 0.f;
    t = fmaf(v1.z, inv, bs[6]); o[6] = t > 0.f ? t : 0.f;
    t = fmaf(v1.w, inv, bs[7]); o[7] = t > 0.f ? t : 0.f;

    float sum = bfv;
    #pragma unroll
    for (int j = 0; j < H2; j++) sum = fmaf(o[j], wf[j], sum);
    out[n] = sum;
}

// ---------------- launch ------------------------------------------------------
extern "C" void kernel_launch(void* const* d_in, const int* in_sizes, int n_in,
                              void* d_out, int out_size) {
    const float* x   = (const float*)d_in[0];
    const int*   ei  = (const int*)d_in[1];
    const float* W1  = (const float*)d_in[2];
    const float* a1s = (const float*)d_in[3];
    const float* a1d = (const float*)d_in[4];
    const float* b1  = (const float*)d_in[5];
    const float* W2  = (const float*)d_in[6];
    const float* a2s = (const float*)d_in[7];
    const float* a2d = (const float*)d_in[8];
    const float* b2  = (const float*)d_in[9];
    const float* Wf  = (const float*)d_in[10];
    const float* bf  = (const float*)d_in[11];
    float* out = (float*)d_out;

    k_detect<<<1, 32>>>(ei);
    k_l1_node<<<(NN + 7) / 8, 256>>>(x, W1, a1s, a1d);      // 8 warps/block, warp/node
    k_edge1<<<(EE + 255) / 256, 256>>>(ei);
    k_l2_node<<<(NN + 255) / 256, 256>>>(W2, a2s, a2d, b1);
    k_edge2<<<(EE + 255) / 256, 256>>>(ei);
    k_final<<<(NN + 255) / 256, 256>>>(Wf, bf, b2, out);
}